// round 1
// baseline (speedup 1.0000x reference)
#include <cuda_runtime.h>

#define SLEN 2048
#define NI   768
#define NH   12
#define DH   64
#define NB   2
#define MTOT (NB * SLEN)   // 4096

// Scratch (device globals: allocation-free)
__device__ float g_Q[NB * NH * SLEN * DH];   // [b,h,s,d]
__device__ float g_K[NB * NH * SLEN * DH];
__device__ float g_V[NB * NH * SLEN * DH];
__device__ float g_O[MTOT * NI];             // [b*s, ni] merged heads

// ---------------------------------------------------------------------------
// Tiled fp32 GEMM: C[M,N] = A[M,K] @ B[K,N] + bias
// MODE 0: A = param (inp), epilogue scatters into g_Q/g_K/g_V per-head layout
// MODE 1: A = g_O, epilogue writes plain C (d_out)
// BM=BN=64, BK=16, 256 threads, 4x4 per thread
// ---------------------------------------------------------------------------
template <int MODE>
__global__ void gemm_kernel(const float* __restrict__ A,
                            const float* __restrict__ B,
                            const float* __restrict__ bias,
                            float* __restrict__ C,
                            int M, int N, int K)
{
    __shared__ float As[16][64];   // transposed A tile: As[k][m]
    __shared__ float Bs[16][64];

    const float* __restrict__ Ap = (MODE == 1) ? g_O : A;

    const int tid = threadIdx.x;
    const int tx = tid & 15;        // N direction
    const int ty = tid >> 4;        // M direction
    const int bm = blockIdx.y * 64;
    const int bn = blockIdx.x * 64;

    const int arow = tid >> 2;            // 0..63
    const int ak   = (tid & 3) << 2;      // 0,4,8,12
    const int brow = tid >> 4;            // 0..15
    const int bcol = (tid & 15) << 2;     // 0..60

    float acc[4][4] = {};

    for (int kt = 0; kt < K; kt += 16) {
        float4 av = *(const float4*)&Ap[(size_t)(bm + arow) * K + kt + ak];
        As[ak + 0][arow] = av.x;
        As[ak + 1][arow] = av.y;
        As[ak + 2][arow] = av.z;
        As[ak + 3][arow] = av.w;
        float4 bv = *(const float4*)&B[(size_t)(kt + brow) * N + bn + bcol];
        *(float4*)&Bs[brow][bcol] = bv;
        __syncthreads();

        #pragma unroll
        for (int k = 0; k < 16; k++) {
            float4 a4 = *(const float4*)&As[k][ty << 2];
            float4 b4 = *(const float4*)&Bs[k][tx << 2];
            float a[4] = {a4.x, a4.y, a4.z, a4.w};
            float b[4] = {b4.x, b4.y, b4.z, b4.w};
            #pragma unroll
            for (int i = 0; i < 4; i++)
                #pragma unroll
                for (int j = 0; j < 4; j++)
                    acc[i][j] += a[i] * b[j];
        }
        __syncthreads();
    }

    if (MODE == 0) {
        // Scatter QKV: column c = h*192 + r ; r<64 -> Q, r<128 -> K, else V
        #pragma unroll
        for (int i = 0; i < 4; i++) {
            int m  = bm + (ty << 2) + i;
            int b  = m >> 11;             // / 2048
            int sI = m & (SLEN - 1);
            #pragma unroll
            for (int j = 0; j < 4; j++) {
                int c = bn + (tx << 2) + j;
                float v = acc[i][j] + bias[c];
                int h = c / 192;
                int r = c - h * 192;
                int w = r >> 6;
                int dd = r & 63;
                float* dst = (w == 0) ? g_Q : (w == 1) ? g_K : g_V;
                dst[(size_t)((b * NH + h) * SLEN + sI) * DH + dd] = v;
            }
        }
    } else {
        #pragma unroll
        for (int i = 0; i < 4; i++) {
            int m = bm + (ty << 2) + i;
            #pragma unroll
            for (int j = 0; j < 4; j++) {
                int c = bn + (tx << 2) + j;
                C[(size_t)m * N + c] = acc[i][j] + bias[c];
            }
        }
    }
}

// ---------------------------------------------------------------------------
// Flash-style attention, fp32. One CTA = (head bh, 64-query tile).
// 256 threads: thread (tr=tid/16, tc=tid&15) owns S rows tr*4+i, cols tc+16*j.
// smem: Qs[64][68], KP[64][68] (K tile, then reused for P), Vs[64][68]
// ---------------------------------------------------------------------------
#define LD 68
#define ATTN_SMEM (3 * 64 * LD * 4)

__global__ void attn_kernel()
{
    extern __shared__ float sm[];
    float* Qs = sm;
    float* KP = sm + 64 * LD;
    float* Vs = sm + 2 * 64 * LD;

    const int tid = threadIdx.x;
    const int bh  = blockIdx.y;          // b*NH + h
    const int q0  = blockIdx.x * 64;

    const float* __restrict__ Qg = g_Q + (size_t)(bh * SLEN + q0) * DH;
    const float* __restrict__ Kg = g_K + (size_t)bh * SLEN * DH;
    const float* __restrict__ Vg = g_V + (size_t)bh * SLEN * DH;

    // Load Q tile (64x64)
    #pragma unroll
    for (int i = 0; i < 4; i++) {
        int f = tid + i * 256;           // float4 index, 1024 total
        int row = f >> 4;
        int c4  = (f & 15) << 2;
        *(float4*)&Qs[row * LD + c4] = *(const float4*)&Qg[row * 64 + c4];
    }

    const int tr = tid >> 4;
    const int tc = tid & 15;

    float Mi[4], Li[4], Oa[4][4];
    #pragma unroll
    for (int i = 0; i < 4; i++) {
        Mi[i] = -1e30f;
        Li[i] = 0.0f;
        #pragma unroll
        for (int j = 0; j < 4; j++) Oa[i][j] = 0.0f;
    }

    for (int kt = 0; kt < SLEN; kt += 64) {
        __syncthreads();   // prior-iter P/V reads done (also covers Q load, 1st iter)

        // Load K and V tiles (64x64 each)
        #pragma unroll
        for (int i = 0; i < 4; i++) {
            int f = tid + i * 256;
            int row = f >> 4;
            int c4  = (f & 15) << 2;
            *(float4*)&KP[row * LD + c4] = *(const float4*)&Kg[(size_t)(kt + row) * 64 + c4];
            *(float4*)&Vs[row * LD + c4] = *(const float4*)&Vg[(size_t)(kt + row) * 64 + c4];
        }
        __syncthreads();

        // S = Q K^T * (1/8)   (rows tr*4+i, cols tc+16*j)
        float s[4][4] = {};
        #pragma unroll
        for (int kk = 0; kk < 64; kk += 4) {
            float4 q4[4], k4[4];
            #pragma unroll
            for (int i = 0; i < 4; i++)
                q4[i] = *(const float4*)&Qs[(tr * 4 + i) * LD + kk];
            #pragma unroll
            for (int j = 0; j < 4; j++)
                k4[j] = *(const float4*)&KP[(tc + 16 * j) * LD + kk];
            #pragma unroll
            for (int i = 0; i < 4; i++)
                #pragma unroll
                for (int j = 0; j < 4; j++)
                    s[i][j] += q4[i].x * k4[j].x + q4[i].y * k4[j].y +
                               q4[i].z * k4[j].z + q4[i].w * k4[j].w;
        }
        __syncthreads();   // everyone done reading K tile from KP

        // Online softmax update; write P into KP
        #pragma unroll
        for (int i = 0; i < 4; i++) {
            #pragma unroll
            for (int j = 0; j < 4; j++) s[i][j] *= 0.125f;

            float rm = fmaxf(fmaxf(s[i][0], s[i][1]), fmaxf(s[i][2], s[i][3]));
            #pragma unroll
            for (int off = 8; off > 0; off >>= 1)
                rm = fmaxf(rm, __shfl_xor_sync(0xffffffffu, rm, off));

            float mn = fmaxf(Mi[i], rm);
            float al = __expf(Mi[i] - mn);
            Mi[i] = mn;

            float rs = 0.0f;
            #pragma unroll
            for (int j = 0; j < 4; j++) {
                s[i][j] = __expf(s[i][j] - mn);
                rs += s[i][j];
            }
            #pragma unroll
            for (int off = 8; off > 0; off >>= 1)
                rs += __shfl_xor_sync(0xffffffffu, rs, off);

            Li[i] = Li[i] * al + rs;
            #pragma unroll
            for (int j = 0; j < 4; j++) Oa[i][j] *= al;

            #pragma unroll
            for (int j = 0; j < 4; j++)
                KP[(tr * 4 + i) * LD + tc + 16 * j] = s[i][j];
        }
        __syncthreads();   // P visible to all

        // O += P @ V  (output cols tc+16*j)
        #pragma unroll 8
        for (int k = 0; k < 64; k++) {
            float p[4], v[4];
            #pragma unroll
            for (int i = 0; i < 4; i++)
                p[i] = KP[(tr * 4 + i) * LD + k];
            #pragma unroll
            for (int j = 0; j < 4; j++)
                v[j] = Vs[k * LD + tc + 16 * j];
            #pragma unroll
            for (int i = 0; i < 4; i++)
                #pragma unroll
                for (int j = 0; j < 4; j++)
                    Oa[i][j] += p[i] * v[j];
        }
    }

    // Normalize & write merged-head output g_O[b*s + q][h*64 + col]
    const int b = bh / NH;
    const int h = bh - b * NH;
    #pragma unroll
    for (int i = 0; i < 4; i++) {
        int q = q0 + tr * 4 + i;
        float inv = 1.0f / Li[i];
        #pragma unroll
        for (int j = 0; j < 4; j++)
            g_O[(size_t)(b * SLEN + q) * NI + h * DH + tc + 16 * j] = Oa[i][j] * inv;
    }
}

// ---------------------------------------------------------------------------
extern "C" void kernel_launch(void* const* d_in, const int* in_sizes, int n_in,
                              void* d_out, int out_size)
{
    const float* inp   = (const float*)d_in[0];
    const float* Wqkv  = (const float*)d_in[1];
    const float* bqkv  = (const float*)d_in[2];
    const float* Wproj = (const float*)d_in[3];
    const float* bproj = (const float*)d_in[4];
    float* out = (float*)d_out;

    cudaFuncSetAttribute(attn_kernel,
                         cudaFuncAttributeMaxDynamicSharedMemorySize, ATTN_SMEM);

    // 1) QKV GEMM + split:  [4096,768] @ [768,2304]
    {
        dim3 grid(3 * NI / 64, MTOT / 64);
        gemm_kernel<0><<<grid, 256>>>(inp, Wqkv, bqkv, nullptr, MTOT, 3 * NI, NI);
    }
    // 2) Attention (flash, online softmax)
    {
        dim3 grid(SLEN / 64, NB * NH);
        attn_kernel<<<grid, 256, ATTN_SMEM>>>();
    }
    // 3) Output projection: [4096,768] @ [768,768]
    {
        dim3 grid(NI / 64, MTOT / 64);
        gemm_kernel<1><<<grid, 256>>>(nullptr, Wproj, bproj, out, MTOT, NI, NI);
    }
}

// round 3
// speedup vs baseline: 3.1135x; 3.1135x over previous
#include <cuda_runtime.h>
#include <cuda_bf16.h>
#include <cstdint>

#define SLEN 2048
#define NI   768
#define NH   12
#define DH   64
#define NB   2
#define MTOT (NB * SLEN)       // 4096
#define KSPLIT (3 * NI)        // 2304
#define NBH (NB * NH)          // 24

typedef __nv_bfloat16  bf16;
typedef __nv_bfloat162 bf162;

// ---------------------------------------------------------------------------
// Device-global scratch (allocation-free)
// ---------------------------------------------------------------------------
__device__ __align__(256) bf16 g_A2[(size_t)MTOT * KSPLIT];    // [m][hi|lo|hi]
__device__ __align__(256) bf16 g_Wq2[(size_t)KSPLIT * KSPLIT]; // [n][hi|hi|lo]
__device__ __align__(256) bf16 g_Wp2[(size_t)NI * KSPLIT];
__device__ __align__(256) bf16 g_Qh[NBH * SLEN * DH];
__device__ __align__(256) bf16 g_Ql[NBH * SLEN * DH];
__device__ __align__(256) bf16 g_Kh[NBH * SLEN * DH];
__device__ __align__(256) bf16 g_Kl[NBH * SLEN * DH];
__device__ __align__(256) bf16 g_Vh[NBH * SLEN * DH];
__device__ __align__(256) bf16 g_Vl[NBH * SLEN * DH];

// ---------------------------------------------------------------------------
// PTX helpers (all plain sm_80+ features: mma.sync, ldmatrix, cp.async)
// ---------------------------------------------------------------------------
__device__ __forceinline__ uint32_t smem_u32(const void* p) {
    uint32_t a;
    asm("{ .reg .u64 t; cvta.to.shared.u64 t, %1; cvt.u32.u64 %0, t; }" : "=r"(a) : "l"(p));
    return a;
}

#define LDSM_X4(r0, r1, r2, r3, addr) \
    asm volatile("ldmatrix.sync.aligned.m8n8.x4.shared.b16 {%0,%1,%2,%3}, [%4];" \
        : "=r"(r0), "=r"(r1), "=r"(r2), "=r"(r3) : "r"(addr))
#define LDSM_X2(r0, r1, addr) \
    asm volatile("ldmatrix.sync.aligned.m8n8.x2.shared.b16 {%0,%1}, [%2];" \
        : "=r"(r0), "=r"(r1) : "r"(addr))
#define LDSM_X2_T(r0, r1, addr) \
    asm volatile("ldmatrix.sync.aligned.m8n8.x2.trans.shared.b16 {%0,%1}, [%2];" \
        : "=r"(r0), "=r"(r1) : "r"(addr))

__device__ __forceinline__ void mma_bf16(float* d, const uint32_t* a, const uint32_t* b) {
    asm volatile(
        "mma.sync.aligned.m16n8k16.row.col.f32.bf16.bf16.f32 "
        "{%0,%1,%2,%3}, {%4,%5,%6,%7}, {%8,%9}, {%0,%1,%2,%3};"
        : "+f"(d[0]), "+f"(d[1]), "+f"(d[2]), "+f"(d[3])
        : "r"(a[0]), "r"(a[1]), "r"(a[2]), "r"(a[3]), "r"(b[0]), "r"(b[1]));
}

#define CP_ASYNC16(sa, gp) \
    asm volatile("cp.async.cg.shared.global [%0], [%1], 16;" :: "r"(sa), "l"(gp))
#define CP_COMMIT() asm volatile("cp.async.commit_group;")
#define CP_WAIT(n)  asm volatile("cp.async.wait_group %0;" :: "n"(n))

__device__ __forceinline__ uint32_t swz(uint32_t base, int row, int chunk) {
    // 128-byte rows; 16B chunk xor-swizzled by row&7
    return base + row * 128 + (((chunk ^ (row & 7))) << 4);
}

__device__ __forceinline__ uint32_t packbf(float x, float y) {
    bf162 t = __floats2bfloat162_rn(x, y);
    return *reinterpret_cast<uint32_t*>(&t);
}

// ---------------------------------------------------------------------------
// Split preps (fp32 -> bf16 hi/lo)
// ---------------------------------------------------------------------------
__global__ void split_act_kernel(const float* __restrict__ src) {
    int idx = blockIdx.x * blockDim.x + threadIdx.x;
    if (idx >= MTOT * NI) return;
    int m = idx / NI, k = idx - (idx / NI) * NI;
    float x = src[idx];
    bf16 hi = __float2bfloat16(x);
    bf16 lo = __float2bfloat16(x - __bfloat162float(hi));
    size_t base = (size_t)m * KSPLIT;
    g_A2[base + k]          = hi;
    g_A2[base + NI + k]     = lo;
    g_A2[base + 2 * NI + k] = hi;
}

// W [768, Ncols] -> dst [Ncols][2304], dst row n: [hi | hi | lo]
__global__ void split_w_kernel(const float* __restrict__ W,
                               bf16* __restrict__ dst, int Ncols) {
    __shared__ float t[32][33];
    int n0 = blockIdx.x * 32, k0 = blockIdx.y * 32;
    #pragma unroll
    for (int i = 0; i < 4; i++) {
        int k = k0 + threadIdx.y + i * 8;
        t[threadIdx.y + i * 8][threadIdx.x] = W[(size_t)k * Ncols + n0 + threadIdx.x];
    }
    __syncthreads();
    #pragma unroll
    for (int i = 0; i < 4; i++) {
        int n = n0 + threadIdx.y + i * 8;
        int k = k0 + threadIdx.x;
        float x = t[threadIdx.x][threadIdx.y + i * 8];
        bf16 hi = __float2bfloat16(x);
        bf16 lo = __float2bfloat16(x - __bfloat162float(hi));
        size_t base = (size_t)n * KSPLIT;
        dst[base + k]          = hi;
        dst[base + NI + k]     = hi;
        dst[base + 2 * NI + k] = lo;
    }
}

// ---------------------------------------------------------------------------
// mma.sync GEMM: C[M,N] = A2[M,2304] @ B2[N,2304]^T (+bias)
// CTA 128x128, BK=64, 256 thr (8 warps 4x2), warp tile 32x64.
// MODE 0: epilogue -> split-bf16 scatter into g_{Q,K,V}{h,l}
// MODE 1: epilogue -> fp32 C
// ---------------------------------------------------------------------------
#define BM 128
#define BN 128
#define BK 64
#define NCH (KSPLIT / BK)         // 36
#define GSTAGE 32768              // A 16K + B 16K
#define GEMM_SMEM (2 * GSTAGE)

template <int MODE>
__global__ __launch_bounds__(256, 2)
void gemm_tc(const bf16* __restrict__ A2, const bf16* __restrict__ B2,
             const float* __restrict__ bias, float* __restrict__ Cout, int Ntot)
{
    extern __shared__ char smem[];
    const uint32_t sb = smem_u32(smem);
    const int tid = threadIdx.x;
    const int warp = tid >> 5;
    const int lane = tid & 31;
    const int wm = (warp >> 1) * 32;
    const int wn = (warp & 1) * 64;
    const int bm = blockIdx.y * BM;
    const int bn = blockIdx.x * BN;

    float acc[2][8][4] = {};

    const char* Ab = (const char*)A2;
    const char* Bb = (const char*)B2;

    auto issue = [&](int c, int st) {
        uint32_t abase = sb + st * GSTAGE;
        uint32_t bbase = abase + 16384;
        #pragma unroll
        for (int i = 0; i < 4; i++) {
            int id = tid + i * 256;
            int r = id >> 3, ch = id & 7;
            CP_ASYNC16(swz(abase, r, ch),
                       Ab + ((size_t)(bm + r) * KSPLIT + c * BK) * 2 + ch * 16);
        }
        #pragma unroll
        for (int i = 0; i < 4; i++) {
            int id = tid + i * 256;
            int r = id >> 3, ch = id & 7;
            CP_ASYNC16(swz(bbase, r, ch),
                       Bb + ((size_t)(bn + r) * KSPLIT + c * BK) * 2 + ch * 16);
        }
        CP_COMMIT();
    };

    issue(0, 0);

    for (int c = 0; c < NCH; c++) {
        const int st = c & 1;
        __syncthreads();
        if (c + 1 < NCH) {
            issue(c + 1, st ^ 1);
            CP_WAIT(1);
        } else {
            CP_WAIT(0);
        }
        __syncthreads();

        uint32_t abase = sb + st * GSTAGE;
        uint32_t bbase = abase + 16384;
        const int t = lane >> 3;

        #pragma unroll
        for (int ks = 0; ks < 4; ks++) {
            uint32_t a[2][4];
            #pragma unroll
            for (int mt = 0; mt < 2; mt++) {
                int row = wm + mt * 16 + (t & 1) * 8 + (lane & 7);
                LDSM_X4(a[mt][0], a[mt][1], a[mt][2], a[mt][3],
                        swz(abase, row, 2 * ks + (t >> 1)));
            }
            #pragma unroll
            for (int nt = 0; nt < 8; nt++) {
                uint32_t b[2];
                int l15 = lane & 15;
                int row = wn + nt * 8 + (l15 & 7);
                LDSM_X2(b[0], b[1], swz(bbase, row, 2 * ks + (l15 >> 3)));
                mma_bf16(acc[0][nt], a[0], b);
                mma_bf16(acc[1][nt], a[1], b);
            }
        }
    }

    // Epilogue (direct from regs)
    #pragma unroll
    for (int mt = 0; mt < 2; mt++) {
        int gr0 = bm + wm + mt * 16 + (lane >> 2);
        #pragma unroll
        for (int nt = 0; nt < 8; nt++) {
            int c0 = bn + wn + nt * 8 + 2 * (lane & 3);
            float b0 = bias[c0], b1 = bias[c0 + 1];
            #pragma unroll
            for (int rr = 0; rr < 2; rr++) {
                int row = gr0 + rr * 8;
                float v0 = acc[mt][nt][rr * 2 + 0] + b0;
                float v1 = acc[mt][nt][rr * 2 + 1] + b1;
                if (MODE == 0) {
                    int h = c0 / 192;
                    int r = c0 - h * 192;
                    int w = r >> 6, dd = r & 63;
                    int b = row >> 11, sI = row & (SLEN - 1);
                    size_t off = ((size_t)((b * NH + h) * SLEN + sI)) * DH + dd;
                    bf16 h0 = __float2bfloat16(v0);
                    bf16 h1 = __float2bfloat16(v1);
                    bf16 l0 = __float2bfloat16(v0 - __bfloat162float(h0));
                    bf16 l1 = __float2bfloat16(v1 - __bfloat162float(h1));
                    bf16 *dh, *dl;
                    if (w == 0)      { dh = g_Qh; dl = g_Ql; }
                    else if (w == 1) { dh = g_Kh; dl = g_Kl; }
                    else             { dh = g_Vh; dl = g_Vl; }
                    *(bf162*)&dh[off] = bf162(h0, h1);
                    *(bf162*)&dl[off] = bf162(l0, l1);
                } else {
                    float2 v = make_float2(v0, v1);
                    *(float2*)&Cout[(size_t)row * Ntot + c0] = v;
                }
            }
        }
    }
}

// ---------------------------------------------------------------------------
// Flash attention on mma.sync (split-bf16, 3-term).
// CTA: 4 warps, Br=64 (16 rows/warp), Bc=64, d=64. grid (32, 24).
// smem: Qh,Ql (8K each) + 2 stages x {Kh,Kl,Vh,Vl} (8K each)
// ---------------------------------------------------------------------------
#define ASTAGE 32768
#define ATTN_SMEM (16384 + 2 * ASTAGE)   // 81920

__global__ __launch_bounds__(128)
void attn_kernel()
{
    extern __shared__ char smem[];
    const uint32_t sb = smem_u32(smem);
    const uint32_t qh_base = sb;
    const uint32_t ql_base = sb + 8192;
    const uint32_t stg_base = sb + 16384;

    const int tid  = threadIdx.x;
    const int warp = tid >> 5;
    const int lane = tid & 31;
    const int bh   = blockIdx.y;
    const int q0   = blockIdx.x * 64;

    const char* Qhg = (const char*)(g_Qh + ((size_t)bh * SLEN + q0) * DH);
    const char* Qlg = (const char*)(g_Ql + ((size_t)bh * SLEN + q0) * DH);
    const char* Khg = (const char*)(g_Kh + (size_t)bh * SLEN * DH);
    const char* Klg = (const char*)(g_Kl + (size_t)bh * SLEN * DH);
    const char* Vhg = (const char*)(g_Vh + (size_t)bh * SLEN * DH);
    const char* Vlg = (const char*)(g_Vl + (size_t)bh * SLEN * DH);

    // Q tiles (rows 0..63, 128B each, swizzled)
    #pragma unroll
    for (int i = 0; i < 8; i++) {
        int id = tid + i * 128;
        int tile = id >> 9;            // 0: hi, 1: lo
        int r = (id >> 3) & 63, ch = id & 7;
        const char* src = (tile == 0 ? Qhg : Qlg) + (size_t)r * 128 + ch * 16;
        CP_ASYNC16(swz(tile == 0 ? qh_base : ql_base, r, ch), src);
    }
    CP_COMMIT();

    auto issue_kv = [&](int kt, int st) {
        uint32_t base = stg_base + st * ASTAGE;
        size_t goff = (size_t)kt * 64 * 128;   // bytes: 64 rows * 128B
        #pragma unroll
        for (int i = 0; i < 16; i++) {
            int id = tid + i * 128;
            int tile = id >> 9;        // 0 Kh, 1 Kl, 2 Vh, 3 Vl
            int r = (id >> 3) & 63, ch = id & 7;
            const char* src;
            if      (tile == 0) src = Khg;
            else if (tile == 1) src = Klg;
            else if (tile == 2) src = Vhg;
            else                src = Vlg;
            src += goff + (size_t)r * 128 + ch * 16;
            CP_ASYNC16(swz(base + tile * 8192, r, ch), src);
        }
        CP_COMMIT();
    };

    issue_kv(0, 0);
    CP_WAIT(0);
    __syncthreads();

    // Q fragments -> regs
    uint32_t qh[4][4], ql[4][4];
    {
        const int t = lane >> 3;
        int row = warp * 16 + (t & 1) * 8 + (lane & 7);
        #pragma unroll
        for (int ks = 0; ks < 4; ks++) {
            LDSM_X4(qh[ks][0], qh[ks][1], qh[ks][2], qh[ks][3],
                    swz(qh_base, row, 2 * ks + (t >> 1)));
            LDSM_X4(ql[ks][0], ql[ks][1], ql[ks][2], ql[ks][3],
                    swz(ql_base, row, 2 * ks + (t >> 1)));
        }
    }

    float m0 = -1e30f, m1 = -1e30f, l0 = 0.f, l1 = 0.f;
    float o[8][4] = {};

    const int NKT = SLEN / 64;     // 32
    for (int kt = 0; kt < NKT; kt++) {
        const int st = kt & 1;
        __syncthreads();
        if (kt + 1 < NKT) {
            issue_kv(kt + 1, st ^ 1);
            CP_WAIT(1);
        } else {
            CP_WAIT(0);
        }
        __syncthreads();

        uint32_t khb = stg_base + st * ASTAGE;
        uint32_t klb = khb + 8192;
        uint32_t vhb = khb + 16384;
        uint32_t vlb = khb + 24576;

        // ---- S = Q K^T (3-term split) ----
        float s[8][4] = {};
        #pragma unroll
        for (int ks = 0; ks < 4; ks++) {
            #pragma unroll
            for (int nt = 0; nt < 8; nt++) {
                int l15 = lane & 15;
                int row = nt * 8 + (l15 & 7);
                int ch = 2 * ks + (l15 >> 3);
                uint32_t bh2[2], bl2[2];
                LDSM_X2(bh2[0], bh2[1], swz(khb, row, ch));
                LDSM_X2(bl2[0], bl2[1], swz(klb, row, ch));
                mma_bf16(s[nt], qh[ks], bh2);
                mma_bf16(s[nt], ql[ks], bh2);
                mma_bf16(s[nt], qh[ks], bl2);
            }
        }

        // ---- online softmax in c-frag space ----
        float rm0 = -1e30f, rm1 = -1e30f;
        #pragma unroll
        for (int nt = 0; nt < 8; nt++) {
            #pragma unroll
            for (int k = 0; k < 4; k++) s[nt][k] *= 0.125f;
            rm0 = fmaxf(rm0, fmaxf(s[nt][0], s[nt][1]));
            rm1 = fmaxf(rm1, fmaxf(s[nt][2], s[nt][3]));
        }
        rm0 = fmaxf(rm0, __shfl_xor_sync(0xffffffffu, rm0, 1));
        rm0 = fmaxf(rm0, __shfl_xor_sync(0xffffffffu, rm0, 2));
        rm1 = fmaxf(rm1, __shfl_xor_sync(0xffffffffu, rm1, 1));
        rm1 = fmaxf(rm1, __shfl_xor_sync(0xffffffffu, rm1, 2));

        float mn0 = fmaxf(m0, rm0), mn1 = fmaxf(m1, rm1);
        float al0 = __expf(m0 - mn0), al1 = __expf(m1 - mn1);
        m0 = mn0; m1 = mn1;

        float rs0 = 0.f, rs1 = 0.f;
        #pragma unroll
        for (int nt = 0; nt < 8; nt++) {
            s[nt][0] = __expf(s[nt][0] - mn0);
            s[nt][1] = __expf(s[nt][1] - mn0);
            s[nt][2] = __expf(s[nt][2] - mn1);
            s[nt][3] = __expf(s[nt][3] - mn1);
            rs0 += s[nt][0] + s[nt][1];
            rs1 += s[nt][2] + s[nt][3];
        }
        rs0 += __shfl_xor_sync(0xffffffffu, rs0, 1);
        rs0 += __shfl_xor_sync(0xffffffffu, rs0, 2);
        rs1 += __shfl_xor_sync(0xffffffffu, rs1, 1);
        rs1 += __shfl_xor_sync(0xffffffffu, rs1, 2);
        l0 = l0 * al0 + rs0;
        l1 = l1 * al1 + rs1;

        #pragma unroll
        for (int nt = 0; nt < 8; nt++) {
            o[nt][0] *= al0; o[nt][1] *= al0;
            o[nt][2] *= al1; o[nt][3] *= al1;
        }

        // ---- O += P V (3-term split) ----
        #pragma unroll
        for (int j = 0; j < 4; j++) {
            uint32_t ph[4], pl[4];
            #pragma unroll
            for (int half = 0; half < 2; half++) {
                float x0 = s[2 * j + half][0], y0 = s[2 * j + half][1];
                float x1 = s[2 * j + half][2], y1 = s[2 * j + half][3];
                bf16 hx0 = __float2bfloat16(x0), hy0 = __float2bfloat16(y0);
                bf16 hx1 = __float2bfloat16(x1), hy1 = __float2bfloat16(y1);
                ph[half * 2 + 0] = packbf(x0, y0);
                ph[half * 2 + 1] = packbf(x1, y1);
                pl[half * 2 + 0] = packbf(x0 - __bfloat162float(hx0),
                                          y0 - __bfloat162float(hy0));
                pl[half * 2 + 1] = packbf(x1 - __bfloat162float(hx1),
                                          y1 - __bfloat162float(hy1));
            }
            // note: ph[0],ph[1] from nt=2j are a0,a1 (k 0..7); ph[2],ph[3] from
            // nt=2j+1 are a2,a3 (k 8..15) — matches m16k16 a-frag layout.
            int l15 = lane & 15;
            int row = j * 16 + (l15 >> 3) * 8 + (l15 & 7);
            #pragma unroll
            for (int nt = 0; nt < 8; nt++) {
                uint32_t vh2[2], vl2[2];
                LDSM_X2_T(vh2[0], vh2[1], swz(vhb, row, nt));
                LDSM_X2_T(vl2[0], vl2[1], swz(vlb, row, nt));
                mma_bf16(o[nt], ph, vh2);
                mma_bf16(o[nt], pl, vh2);
                mma_bf16(o[nt], ph, vl2);
            }
        }
    }

    // ---- epilogue -> g_A2 [m][hi|lo|hi] ----
    float inv0 = 1.0f / l0, inv1 = 1.0f / l1;
    const int b = bh / NH, h = bh - (bh / NH) * NH;
    const int qr = q0 + warp * 16 + (lane >> 2);
    #pragma unroll
    for (int rr = 0; rr < 2; rr++) {
        size_t m = (size_t)b * SLEN + qr + rr * 8;
        float inv = rr ? inv1 : inv0;
        #pragma unroll
        for (int nt = 0; nt < 8; nt++) {
            int c = h * DH + nt * 8 + 2 * (lane & 3);
            float v0 = o[nt][rr * 2 + 0] * inv;
            float v1 = o[nt][rr * 2 + 1] * inv;
            bf16 h0 = __float2bfloat16(v0);
            bf16 h1 = __float2bfloat16(v1);
            bf16 e0 = __float2bfloat16(v0 - __bfloat162float(h0));
            bf16 e1 = __float2bfloat16(v1 - __bfloat162float(h1));
            bf162 hi2(h0, h1), lo2(e0, e1);
            size_t base = m * KSPLIT;
            *(bf162*)&g_A2[base + c]            = hi2;
            *(bf162*)&g_A2[base + NI + c]       = lo2;
            *(bf162*)&g_A2[base + 2 * NI + c]   = hi2;
        }
    }
}

// ---------------------------------------------------------------------------
extern "C" void kernel_launch(void* const* d_in, const int* in_sizes, int n_in,
                              void* d_out, int out_size)
{
    const float* inp   = (const float*)d_in[0];
    const float* Wqkv  = (const float*)d_in[1];
    const float* bqkv  = (const float*)d_in[2];
    const float* Wproj = (const float*)d_in[3];
    const float* bproj = (const float*)d_in[4];
    float* out = (float*)d_out;

    bf16 *a2, *wq2, *wp2;
    cudaGetSymbolAddress((void**)&a2,  g_A2);
    cudaGetSymbolAddress((void**)&wq2, g_Wq2);
    cudaGetSymbolAddress((void**)&wp2, g_Wp2);

    cudaFuncSetAttribute(gemm_tc<0>,
                         cudaFuncAttributeMaxDynamicSharedMemorySize, GEMM_SMEM);
    cudaFuncSetAttribute(gemm_tc<1>,
                         cudaFuncAttributeMaxDynamicSharedMemorySize, GEMM_SMEM);
    cudaFuncSetAttribute(attn_kernel,
                         cudaFuncAttributeMaxDynamicSharedMemorySize, ATTN_SMEM);

    // 1) splits
    {
        int n = MTOT * NI;
        split_act_kernel<<<(n + 255) / 256, 256>>>(inp);
        dim3 blk(32, 8);
        split_w_kernel<<<dim3(KSPLIT / 32, NI / 32), blk>>>(Wqkv, wq2, KSPLIT);
        split_w_kernel<<<dim3(NI / 32, NI / 32), blk>>>(Wproj, wp2, NI);
    }
    // 2) QKV GEMM + split scatter into Q/K/V hi/lo
    {
        dim3 grid(KSPLIT / BN, MTOT / BM);   // (18, 32)
        gemm_tc<0><<<grid, 256, GEMM_SMEM>>>(a2, wq2, bqkv, nullptr, KSPLIT);
    }
    // 3) Flash attention (mma.sync), writes A2 for proj
    {
        dim3 grid(SLEN / 64, NBH);           // (32, 24)
        attn_kernel<<<grid, 128, ATTN_SMEM>>>();
    }
    // 4) proj GEMM -> out
    {
        dim3 grid(NI / BN, MTOT / BM);       // (6, 32)
        gemm_tc<1><<<grid, 256, GEMM_SMEM>>>(a2, wp2, bproj, out, NI);
    }
}

// round 5
// speedup vs baseline: 3.2855x; 1.0552x over previous
#include <cuda_runtime.h>
#include <cuda_bf16.h>
#include <cstdint>

#define SLEN 2048
#define NI   768
#define NH   12
#define DH   64
#define NB   2
#define MTOT (NB * SLEN)       // 4096
#define KSPLIT (3 * NI)        // 2304
#define NBH (NB * NH)          // 24

typedef __nv_bfloat16  bf16;
typedef __nv_bfloat162 bf162;

// ---------------------------------------------------------------------------
// Device-global scratch (allocation-free)
// ---------------------------------------------------------------------------
__device__ __align__(256) bf16 g_A2[(size_t)MTOT * KSPLIT];    // [m][hi|lo|hi]
__device__ __align__(256) bf16 g_Wq2[(size_t)KSPLIT * KSPLIT]; // [n][hi|hi|lo]
__device__ __align__(256) bf16 g_Wp2[(size_t)NI * KSPLIT];
__device__ __align__(256) bf16 g_Qh[NBH * SLEN * DH];
__device__ __align__(256) bf16 g_Ql[NBH * SLEN * DH];
__device__ __align__(256) bf16 g_Kh[NBH * SLEN * DH];
__device__ __align__(256) bf16 g_Kl[NBH * SLEN * DH];
__device__ __align__(256) bf16 g_Vh[NBH * SLEN * DH];
__device__ __align__(256) bf16 g_Vl[NBH * SLEN * DH];

// ---------------------------------------------------------------------------
// PTX helpers (sm_80+ features only: mma.sync, ldmatrix, cp.async)
// ---------------------------------------------------------------------------
__device__ __forceinline__ uint32_t smem_u32(const void* p) {
    uint32_t a;
    asm("{ .reg .u64 t; cvta.to.shared.u64 t, %1; cvt.u32.u64 %0, t; }" : "=r"(a) : "l"(p));
    return a;
}

#define LDSM_X4(r0, r1, r2, r3, addr) \
    asm volatile("ldmatrix.sync.aligned.m8n8.x4.shared.b16 {%0,%1,%2,%3}, [%4];" \
        : "=r"(r0), "=r"(r1), "=r"(r2), "=r"(r3) : "r"(addr))
#define LDSM_X4_T(r0, r1, r2, r3, addr) \
    asm volatile("ldmatrix.sync.aligned.m8n8.x4.trans.shared.b16 {%0,%1,%2,%3}, [%4];" \
        : "=r"(r0), "=r"(r1), "=r"(r2), "=r"(r3) : "r"(addr))

__device__ __forceinline__ void mma_bf16(float* d, const uint32_t* a, const uint32_t* b) {
    asm volatile(
        "mma.sync.aligned.m16n8k16.row.col.f32.bf16.bf16.f32 "
        "{%0,%1,%2,%3}, {%4,%5,%6,%7}, {%8,%9}, {%0,%1,%2,%3};"
        : "+f"(d[0]), "+f"(d[1]), "+f"(d[2]), "+f"(d[3])
        : "r"(a[0]), "r"(a[1]), "r"(a[2]), "r"(a[3]), "r"(b[0]), "r"(b[1]));
}

#define CP_ASYNC16(sa, gp) \
    asm volatile("cp.async.cg.shared.global [%0], [%1], 16;" :: "r"(sa), "l"(gp))
#define CP_COMMIT() asm volatile("cp.async.commit_group;")
#define CP_WAIT(n)  asm volatile("cp.async.wait_group %0;" :: "n"(n))

__device__ __forceinline__ uint32_t swz(uint32_t base, int row, int chunk) {
    return base + row * 128 + (((chunk ^ (row & 7))) << 4);
}

__device__ __forceinline__ uint32_t packbf(float x, float y) {
    bf162 t = __floats2bfloat162_rn(x, y);
    return *reinterpret_cast<uint32_t*>(&t);
}

// ---------------------------------------------------------------------------
// Split preps
// ---------------------------------------------------------------------------
__global__ void split_act_kernel(const float* __restrict__ src) {
    int idx = blockIdx.x * blockDim.x + threadIdx.x;
    if (idx >= MTOT * NI) return;
    int m = idx / NI, k = idx - (idx / NI) * NI;
    float x = src[idx];
    bf16 hi = __float2bfloat16(x);
    bf16 lo = __float2bfloat16(x - __bfloat162float(hi));
    size_t base = (size_t)m * KSPLIT;
    g_A2[base + k]          = hi;
    g_A2[base + NI + k]     = lo;
    g_A2[base + 2 * NI + k] = hi;
}

__global__ void split_w_kernel(const float* __restrict__ W,
                               bf16* __restrict__ dst, int Ncols) {
    __shared__ float t[32][33];
    int n0 = blockIdx.x * 32, k0 = blockIdx.y * 32;
    #pragma unroll
    for (int i = 0; i < 4; i++) {
        int k = k0 + threadIdx.y + i * 8;
        t[threadIdx.y + i * 8][threadIdx.x] = W[(size_t)k * Ncols + n0 + threadIdx.x];
    }
    __syncthreads();
    #pragma unroll
    for (int i = 0; i < 4; i++) {
        int n = n0 + threadIdx.y + i * 8;
        int k = k0 + threadIdx.x;
        float x = t[threadIdx.x][threadIdx.y + i * 8];
        bf16 hi = __float2bfloat16(x);
        bf16 lo = __float2bfloat16(x - __bfloat162float(hi));
        size_t base = (size_t)n * KSPLIT;
        dst[base + k]          = hi;
        dst[base + NI + k]     = hi;
        dst[base + 2 * NI + k] = lo;
    }
}

// ---------------------------------------------------------------------------
// mma.sync GEMM: C[M,N] = A2[M,2304] @ B2[N,2304]^T (+bias)
// CTA 128x128, BK=64, 3-stage cp.async, 8 warps (4x2), warp 32x64, x4 ldsm.
// ---------------------------------------------------------------------------
#define BM 128
#define BN 128
#define BK 64
#define NCH (KSPLIT / BK)         // 36
#define GSTAGE 32768              // A 16K + B 16K
#define GEMM_SMEM (3 * GSTAGE)    // 98304

template <int MODE>
__global__ __launch_bounds__(256, 2)
void gemm_tc(const bf16* __restrict__ A2, const bf16* __restrict__ B2,
             const float* __restrict__ bias, float* __restrict__ Cout, int Ntot)
{
    extern __shared__ char smem[];
    const uint32_t sb = smem_u32(smem);
    const int tid = threadIdx.x;
    const int warp = tid >> 5;
    const int lane = tid & 31;
    const int wm = (warp >> 1) * 32;
    const int wn = (warp & 1) * 64;
    const int bm = blockIdx.y * BM;
    const int bn = blockIdx.x * BN;

    float acc[2][8][4] = {};

    const char* Ab = (const char*)A2;
    const char* Bb = (const char*)B2;

    auto issue = [&](int c, int st) {
        uint32_t abase = sb + st * GSTAGE;
        uint32_t bbase = abase + 16384;
        #pragma unroll
        for (int i = 0; i < 4; i++) {
            int id = tid + i * 256;
            int r = id >> 3, ch = id & 7;
            CP_ASYNC16(swz(abase, r, ch),
                       Ab + ((size_t)(bm + r) * KSPLIT + c * BK) * 2 + ch * 16);
        }
        #pragma unroll
        for (int i = 0; i < 4; i++) {
            int id = tid + i * 256;
            int r = id >> 3, ch = id & 7;
            CP_ASYNC16(swz(bbase, r, ch),
                       Bb + ((size_t)(bn + r) * KSPLIT + c * BK) * 2 + ch * 16);
        }
        CP_COMMIT();
    };

    issue(0, 0);
    issue(1, 1);

    for (int c = 0; c < NCH; c++) {
        const int st = c - (c / 3) * 3;
        CP_WAIT(1);               // pending {c, c+1}; retire c
        __syncthreads();          // data visible + stage (c+2)%3 free to overwrite
        if (c + 2 < NCH) issue(c + 2, (c + 2) - ((c + 2) / 3) * 3);
        else CP_COMMIT();         // keep group count uniform

        uint32_t abase = sb + st * GSTAGE;
        uint32_t bbase = abase + 16384;
        const int t = lane >> 3;

        #pragma unroll
        for (int ks = 0; ks < 4; ks++) {
            uint32_t a[2][4];
            #pragma unroll
            for (int mt = 0; mt < 2; mt++) {
                int row = wm + mt * 16 + (t & 1) * 8 + (lane & 7);
                LDSM_X4(a[mt][0], a[mt][1], a[mt][2], a[mt][3],
                        swz(abase, row, 2 * ks + (t >> 1)));
            }
            #pragma unroll
            for (int ntp = 0; ntp < 4; ntp++) {
                uint32_t b4[4];
                int row = wn + (2 * ntp + ((lane >> 4) & 1)) * 8 + (lane & 7);
                LDSM_X4(b4[0], b4[1], b4[2], b4[3],
                        swz(bbase, row, 2 * ks + ((lane >> 3) & 1)));
                mma_bf16(acc[0][2 * ntp + 0], a[0], b4 + 0);
                mma_bf16(acc[1][2 * ntp + 0], a[1], b4 + 0);
                mma_bf16(acc[0][2 * ntp + 1], a[0], b4 + 2);
                mma_bf16(acc[1][2 * ntp + 1], a[1], b4 + 2);
            }
        }
        __syncthreads();          // done reading stage st before it's refilled
    }

    // Epilogue
    #pragma unroll
    for (int mt = 0; mt < 2; mt++) {
        int gr0 = bm + wm + mt * 16 + (lane >> 2);
        #pragma unroll
        for (int nt = 0; nt < 8; nt++) {
            int c0 = bn + wn + nt * 8 + 2 * (lane & 3);
            float b0 = bias[c0], b1 = bias[c0 + 1];
            #pragma unroll
            for (int rr = 0; rr < 2; rr++) {
                int row = gr0 + rr * 8;
                float v0 = acc[mt][nt][rr * 2 + 0] + b0;
                float v1 = acc[mt][nt][rr * 2 + 1] + b1;
                if (MODE == 0) {
                    int h = c0 / 192;
                    int r = c0 - h * 192;
                    int w = r >> 6, dd = r & 63;
                    int b = row >> 11, sI = row & (SLEN - 1);
                    size_t off = ((size_t)((b * NH + h) * SLEN + sI)) * DH + dd;
                    bf16 h0 = __float2bfloat16(v0);
                    bf16 h1 = __float2bfloat16(v1);
                    bf16 l0 = __float2bfloat16(v0 - __bfloat162float(h0));
                    bf16 l1 = __float2bfloat16(v1 - __bfloat162float(h1));
                    bf16 *dh, *dl;
                    if (w == 0)      { dh = g_Qh; dl = g_Ql; }
                    else if (w == 1) { dh = g_Kh; dl = g_Kl; }
                    else             { dh = g_Vh; dl = g_Vl; }
                    *(bf162*)&dh[off] = bf162(h0, h1);
                    *(bf162*)&dl[off] = bf162(l0, l1);
                } else {
                    float2 v = make_float2(v0, v1);
                    *(float2*)&Cout[(size_t)row * Ntot + c0] = v;
                }
            }
        }
    }
}

// ---------------------------------------------------------------------------
// Flash attention on mma.sync (split-bf16, 3-term).
// CTA: 8 warps, Br=128 (16 rows/warp), Bc=64, d=64. grid (16, 24).
// smem: Qh,Ql (16K each) + 2 stages x {Kh,Kl,Vh,Vl} (8K each)
// ---------------------------------------------------------------------------
#define ASTAGE 32768
#define ATTN_SMEM (32768 + 2 * ASTAGE)   // 98304

__global__ __launch_bounds__(256, 2)
void attn_kernel()
{
    extern __shared__ char smem[];
    const uint32_t sb = smem_u32(smem);
    const uint32_t qh_base = sb;
    const uint32_t ql_base = sb + 16384;
    const uint32_t stg_base = sb + 32768;

    const int tid  = threadIdx.x;
    const int warp = tid >> 5;
    const int lane = tid & 31;
    const int bh   = blockIdx.y;
    const int q0   = blockIdx.x * 128;

    const char* Qhg = (const char*)(g_Qh + ((size_t)bh * SLEN + q0) * DH);
    const char* Qlg = (const char*)(g_Ql + ((size_t)bh * SLEN + q0) * DH);
    const char* Khg = (const char*)(g_Kh + (size_t)bh * SLEN * DH);
    const char* Klg = (const char*)(g_Kl + (size_t)bh * SLEN * DH);
    const char* Vhg = (const char*)(g_Vh + (size_t)bh * SLEN * DH);
    const char* Vlg = (const char*)(g_Vl + (size_t)bh * SLEN * DH);

    // Q tiles: 2 x 128 rows x 128B
    #pragma unroll
    for (int i = 0; i < 8; i++) {
        int id = tid + i * 256;
        int tile = id >> 10;           // 0: hi, 1: lo (1024 chunks each)
        int r = (id >> 3) & 127, ch = id & 7;
        const char* src = (tile == 0 ? Qhg : Qlg) + (size_t)r * 128 + ch * 16;
        CP_ASYNC16(swz(tile == 0 ? qh_base : ql_base, r, ch), src);
    }
    CP_COMMIT();

    auto issue_kv = [&](int kt, int st) {
        uint32_t base = stg_base + st * ASTAGE;
        size_t goff = (size_t)kt * 64 * 128;
        #pragma unroll
        for (int i = 0; i < 8; i++) {
            int id = tid + i * 256;
            int tile = id >> 9;        // 0 Kh, 1 Kl, 2 Vh, 3 Vl (512 chunks each)
            int r = (id >> 3) & 63, ch = id & 7;
            const char* src;
            if      (tile == 0) src = Khg;
            else if (tile == 1) src = Klg;
            else if (tile == 2) src = Vhg;
            else                src = Vlg;
            src += goff + (size_t)r * 128 + ch * 16;
            CP_ASYNC16(swz(base + tile * 8192, r, ch), src);
        }
        CP_COMMIT();
    };

    issue_kv(0, 0);
    CP_WAIT(0);
    __syncthreads();

    // Q fragments -> regs
    uint32_t qh[4][4], ql[4][4];
    {
        const int t = lane >> 3;
        int row = warp * 16 + (t & 1) * 8 + (lane & 7);
        #pragma unroll
        for (int ks = 0; ks < 4; ks++) {
            LDSM_X4(qh[ks][0], qh[ks][1], qh[ks][2], qh[ks][3],
                    swz(qh_base, row, 2 * ks + (t >> 1)));
            LDSM_X4(ql[ks][0], ql[ks][1], ql[ks][2], ql[ks][3],
                    swz(ql_base, row, 2 * ks + (t >> 1)));
        }
    }

    float m0 = -1e30f, m1 = -1e30f, l0 = 0.f, l1 = 0.f;
    float o[8][4] = {};

    const int NKT = SLEN / 64;     // 32
    for (int kt = 0; kt < NKT; kt++) {
        const int st = kt & 1;
        __syncthreads();
        if (kt + 1 < NKT) {
            issue_kv(kt + 1, st ^ 1);
            CP_WAIT(1);
        } else {
            CP_WAIT(0);
        }
        __syncthreads();

        uint32_t khb = stg_base + st * ASTAGE;
        uint32_t klb = khb + 8192;
        uint32_t vhb = khb + 16384;
        uint32_t vlb = khb + 24576;

        // ---- S = Q K^T (3-term split), x4 K loads ----
        float s[8][4] = {};
        #pragma unroll
        for (int ks = 0; ks < 4; ks++) {
            #pragma unroll
            for (int ntp = 0; ntp < 4; ntp++) {
                int row = (2 * ntp + ((lane >> 4) & 1)) * 8 + (lane & 7);
                int ch = 2 * ks + ((lane >> 3) & 1);
                uint32_t bh4[4], bl4[4];
                LDSM_X4(bh4[0], bh4[1], bh4[2], bh4[3], swz(khb, row, ch));
                LDSM_X4(bl4[0], bl4[1], bl4[2], bl4[3], swz(klb, row, ch));
                mma_bf16(s[2 * ntp + 0], qh[ks], bh4 + 0);
                mma_bf16(s[2 * ntp + 0], ql[ks], bh4 + 0);
                mma_bf16(s[2 * ntp + 0], qh[ks], bl4 + 0);
                mma_bf16(s[2 * ntp + 1], qh[ks], bh4 + 2);
                mma_bf16(s[2 * ntp + 1], ql[ks], bh4 + 2);
                mma_bf16(s[2 * ntp + 1], qh[ks], bl4 + 2);
            }
        }

        // ---- online softmax ----
        float rm0 = -1e30f, rm1 = -1e30f;
        #pragma unroll
        for (int nt = 0; nt < 8; nt++) {
            #pragma unroll
            for (int k = 0; k < 4; k++) s[nt][k] *= 0.125f;
            rm0 = fmaxf(rm0, fmaxf(s[nt][0], s[nt][1]));
            rm1 = fmaxf(rm1, fmaxf(s[nt][2], s[nt][3]));
        }
        rm0 = fmaxf(rm0, __shfl_xor_sync(0xffffffffu, rm0, 1));
        rm0 = fmaxf(rm0, __shfl_xor_sync(0xffffffffu, rm0, 2));
        rm1 = fmaxf(rm1, __shfl_xor_sync(0xffffffffu, rm1, 1));
        rm1 = fmaxf(rm1, __shfl_xor_sync(0xffffffffu, rm1, 2));

        float mn0 = fmaxf(m0, rm0), mn1 = fmaxf(m1, rm1);
        float al0 = __expf(m0 - mn0), al1 = __expf(m1 - mn1);
        m0 = mn0; m1 = mn1;

        float rs0 = 0.f, rs1 = 0.f;
        #pragma unroll
        for (int nt = 0; nt < 8; nt++) {
            s[nt][0] = __expf(s[nt][0] - mn0);
            s[nt][1] = __expf(s[nt][1] - mn0);
            s[nt][2] = __expf(s[nt][2] - mn1);
            s[nt][3] = __expf(s[nt][3] - mn1);
            rs0 += s[nt][0] + s[nt][1];
            rs1 += s[nt][2] + s[nt][3];
        }
        rs0 += __shfl_xor_sync(0xffffffffu, rs0, 1);
        rs0 += __shfl_xor_sync(0xffffffffu, rs0, 2);
        rs1 += __shfl_xor_sync(0xffffffffu, rs1, 1);
        rs1 += __shfl_xor_sync(0xffffffffu, rs1, 2);
        l0 = l0 * al0 + rs0;
        l1 = l1 * al1 + rs1;

        #pragma unroll
        for (int nt = 0; nt < 8; nt++) {
            o[nt][0] *= al0; o[nt][1] *= al0;
            o[nt][2] *= al1; o[nt][3] *= al1;
        }

        // ---- O += P V (3-term split), x4 trans V loads ----
        #pragma unroll
        for (int j = 0; j < 4; j++) {
            uint32_t ph[4], pl[4];
            #pragma unroll
            for (int half = 0; half < 2; half++) {
                float x0 = s[2 * j + half][0], y0 = s[2 * j + half][1];
                float x1 = s[2 * j + half][2], y1 = s[2 * j + half][3];
                bf16 hx0 = __float2bfloat16(x0), hy0 = __float2bfloat16(y0);
                bf16 hx1 = __float2bfloat16(x1), hy1 = __float2bfloat16(y1);
                ph[half * 2 + 0] = packbf(x0, y0);
                ph[half * 2 + 1] = packbf(x1, y1);
                pl[half * 2 + 0] = packbf(x0 - __bfloat162float(hx0),
                                          y0 - __bfloat162float(hy0));
                pl[half * 2 + 1] = packbf(x1 - __bfloat162float(hx1),
                                          y1 - __bfloat162float(hy1));
            }
            int row = j * 16 + ((lane >> 3) & 1) * 8 + (lane & 7);
            #pragma unroll
            for (int ntp = 0; ntp < 4; ntp++) {
                int ch = 2 * ntp + ((lane >> 4) & 1);
                uint32_t vh4[4], vl4[4];
                LDSM_X4_T(vh4[0], vh4[1], vh4[2], vh4[3], swz(vhb, row, ch));
                LDSM_X4_T(vl4[0], vl4[1], vl4[2], vl4[3], swz(vlb, row, ch));
                mma_bf16(o[2 * ntp + 0], ph, vh4 + 0);
                mma_bf16(o[2 * ntp + 0], pl, vh4 + 0);
                mma_bf16(o[2 * ntp + 0], ph, vl4 + 0);
                mma_bf16(o[2 * ntp + 1], ph, vh4 + 2);
                mma_bf16(o[2 * ntp + 1], pl, vh4 + 2);
                mma_bf16(o[2 * ntp + 1], ph, vl4 + 2);
            }
        }
    }

    // ---- epilogue -> g_A2 [m][hi|lo|hi] ----
    float inv0 = 1.0f / l0, inv1 = 1.0f / l1;
    const int b = bh / NH, h = bh - (bh / NH) * NH;
    const int qr = q0 + warp * 16 + (lane >> 2);
    #pragma unroll
    for (int rr = 0; rr < 2; rr++) {
        size_t m = (size_t)b * SLEN + qr + rr * 8;
        float inv = rr ? inv1 : inv0;
        #pragma unroll
        for (int nt = 0; nt < 8; nt++) {
            int c = h * DH + nt * 8 + 2 * (lane & 3);
            float v0 = o[nt][rr * 2 + 0] * inv;
            float v1 = o[nt][rr * 2 + 1] * inv;
            bf16 h0 = __float2bfloat16(v0);
            bf16 h1 = __float2bfloat16(v1);
            bf16 e0 = __float2bfloat16(v0 - __bfloat162float(h0));
            bf16 e1 = __float2bfloat16(v1 - __bfloat162float(h1));
            bf162 hi2(h0, h1), lo2(e0, e1);
            size_t base = m * KSPLIT;
            *(bf162*)&g_A2[base + c]            = hi2;
            *(bf162*)&g_A2[base + NI + c]       = lo2;
            *(bf162*)&g_A2[base + 2 * NI + c]   = hi2;
        }
    }
}

// ---------------------------------------------------------------------------
extern "C" void kernel_launch(void* const* d_in, const int* in_sizes, int n_in,
                              void* d_out, int out_size)
{
    const float* inp   = (const float*)d_in[0];
    const float* Wqkv  = (const float*)d_in[1];
    const float* bqkv  = (const float*)d_in[2];
    const float* Wproj = (const float*)d_in[3];
    const float* bproj = (const float*)d_in[4];
    float* out = (float*)d_out;

    bf16 *a2, *wq2, *wp2;
    cudaGetSymbolAddress((void**)&a2,  g_A2);
    cudaGetSymbolAddress((void**)&wq2, g_Wq2);
    cudaGetSymbolAddress((void**)&wp2, g_Wp2);

    cudaFuncSetAttribute(gemm_tc<0>,
                         cudaFuncAttributeMaxDynamicSharedMemorySize, GEMM_SMEM);
    cudaFuncSetAttribute(gemm_tc<1>,
                         cudaFuncAttributeMaxDynamicSharedMemorySize, GEMM_SMEM);
    cudaFuncSetAttribute(attn_kernel,
                         cudaFuncAttributeMaxDynamicSharedMemorySize, ATTN_SMEM);

    // 1) splits
    {
        int n = MTOT * NI;
        split_act_kernel<<<(n + 255) / 256, 256>>>(inp);
        dim3 blk(32, 8);
        split_w_kernel<<<dim3(KSPLIT / 32, NI / 32), blk>>>(Wqkv, wq2, KSPLIT);
        split_w_kernel<<<dim3(NI / 32, NI / 32), blk>>>(Wproj, wp2, NI);
    }
    // 2) QKV GEMM + split scatter into Q/K/V hi/lo
    {
        dim3 grid(KSPLIT / BN, MTOT / BM);   // (18, 32)
        gemm_tc<0><<<grid, 256, GEMM_SMEM>>>(a2, wq2, bqkv, nullptr, KSPLIT);
    }
    // 3) Flash attention (mma.sync), writes A2 for proj
    {
        dim3 grid(SLEN / 128, NBH);          // (16, 24)
        attn_kernel<<<grid, 256, ATTN_SMEM>>>();
    }
    // 4) proj GEMM -> out
    {
        dim3 grid(NI / BN, MTOT / BM);       // (6, 32)
        gemm_tc<1><<<grid, 256, GEMM_SMEM>>>(a2, wp2, bproj, out, NI);
    }
}

// round 6
// speedup vs baseline: 3.3940x; 1.0330x over previous
#include <cuda_runtime.h>
#include <cuda_bf16.h>
#include <cstdint>

#define SLEN 2048
#define NI   768
#define NH   12
#define DH   64
#define NB   2
#define MTOT (NB * SLEN)       // 4096
#define NBH (NB * NH)          // 24

typedef __nv_bfloat16  bf16;
typedef __nv_bfloat162 bf162;

// scale folded into Q: (1/8) * log2(e)
#define QSCALE 0.1803368801111725f

// ---------------------------------------------------------------------------
// Device-global scratch (allocation-free).  Activations/weights stored as two
// sections (hi, lo); the GEMM loader remaps logical K-chunks onto sections:
//   A sections {hi, lo, hi} x B sections {hi, hi, lo}  -> 3-term split product
// ---------------------------------------------------------------------------
__device__ __align__(256) bf16 g_Ah[(size_t)MTOT * NI];
__device__ __align__(256) bf16 g_Al[(size_t)MTOT * NI];
__device__ __align__(256) bf16 g_Wqh[(size_t)(3 * NI) * NI];  // [n][k] n=2304
__device__ __align__(256) bf16 g_Wql[(size_t)(3 * NI) * NI];
__device__ __align__(256) bf16 g_Wph[(size_t)NI * NI];
__device__ __align__(256) bf16 g_Wpl[(size_t)NI * NI];
__device__ __align__(256) bf16 g_Qh[NBH * SLEN * DH];   // pre-scaled by QSCALE
__device__ __align__(256) bf16 g_Ql[NBH * SLEN * DH];
__device__ __align__(256) bf16 g_Kh[NBH * SLEN * DH];
__device__ __align__(256) bf16 g_Kl[NBH * SLEN * DH];
__device__ __align__(256) bf16 g_Vh[NBH * SLEN * DH];
__device__ __align__(256) bf16 g_Vl[NBH * SLEN * DH];

// ---------------------------------------------------------------------------
// PTX helpers (sm_80+ only)
// ---------------------------------------------------------------------------
__device__ __forceinline__ uint32_t smem_u32(const void* p) {
    uint32_t a;
    asm("{ .reg .u64 t; cvta.to.shared.u64 t, %1; cvt.u32.u64 %0, t; }" : "=r"(a) : "l"(p));
    return a;
}

#define LDSM_X4(r0, r1, r2, r3, addr) \
    asm volatile("ldmatrix.sync.aligned.m8n8.x4.shared.b16 {%0,%1,%2,%3}, [%4];" \
        : "=r"(r0), "=r"(r1), "=r"(r2), "=r"(r3) : "r"(addr))
#define LDSM_X4_T(r0, r1, r2, r3, addr) \
    asm volatile("ldmatrix.sync.aligned.m8n8.x4.trans.shared.b16 {%0,%1,%2,%3}, [%4];" \
        : "=r"(r0), "=r"(r1), "=r"(r2), "=r"(r3) : "r"(addr))

__device__ __forceinline__ void mma_bf16(float* d, const uint32_t* a, const uint32_t* b) {
    asm volatile(
        "mma.sync.aligned.m16n8k16.row.col.f32.bf16.bf16.f32 "
        "{%0,%1,%2,%3}, {%4,%5,%6,%7}, {%8,%9}, {%0,%1,%2,%3};"
        : "+f"(d[0]), "+f"(d[1]), "+f"(d[2]), "+f"(d[3])
        : "r"(a[0]), "r"(a[1]), "r"(a[2]), "r"(a[3]), "r"(b[0]), "r"(b[1]));
}

#define CP_ASYNC16(sa, gp) \
    asm volatile("cp.async.cg.shared.global [%0], [%1], 16;" :: "r"(sa), "l"(gp))
#define CP_COMMIT() asm volatile("cp.async.commit_group;")
#define CP_WAIT(n)  asm volatile("cp.async.wait_group %0;" :: "n"(n))

__device__ __forceinline__ uint32_t swz(uint32_t base, int row, int chunk) {
    return base + row * 128 + (((chunk ^ (row & 7))) << 4);
}

__device__ __forceinline__ uint32_t packbf(float x, float y) {
    bf162 t = __floats2bfloat162_rn(x, y);
    return *reinterpret_cast<uint32_t*>(&t);
}

__device__ __forceinline__ float ex2(float x) {
    float y;
    asm("ex2.approx.f32 %0, %1;" : "=f"(y) : "f"(x));
    return y;
}

// ---------------------------------------------------------------------------
// Split preps
// ---------------------------------------------------------------------------
__global__ void split_act_kernel(const float* __restrict__ src) {
    int idx = blockIdx.x * blockDim.x + threadIdx.x;
    if (idx >= MTOT * NI) return;
    float x = src[idx];
    bf16 hi = __float2bfloat16(x);
    bf16 lo = __float2bfloat16(x - __bfloat162float(hi));
    g_Ah[idx] = hi;
    g_Al[idx] = lo;
}

// W [768, Ncols] -> hi/lo [Ncols][768] (transposed)
__global__ void split_w_kernel(const float* __restrict__ W,
                               bf16* __restrict__ dh, bf16* __restrict__ dl,
                               int Ncols) {
    __shared__ float t[32][33];
    int n0 = blockIdx.x * 32, k0 = blockIdx.y * 32;
    #pragma unroll
    for (int i = 0; i < 4; i++) {
        int k = k0 + threadIdx.y + i * 8;
        t[threadIdx.y + i * 8][threadIdx.x] = W[(size_t)k * Ncols + n0 + threadIdx.x];
    }
    __syncthreads();
    #pragma unroll
    for (int i = 0; i < 4; i++) {
        int n = n0 + threadIdx.y + i * 8;
        int k = k0 + threadIdx.x;
        float x = t[threadIdx.x][threadIdx.y + i * 8];
        bf16 hi = __float2bfloat16(x);
        bf16 lo = __float2bfloat16(x - __bfloat162float(hi));
        dh[(size_t)n * NI + k] = hi;
        dl[(size_t)n * NI + k] = lo;
    }
}

// ---------------------------------------------------------------------------
// mma.sync GEMM: C[M,N] = sum over 36 logical chunks of A_sec @ B_sec^T (+bias)
// CTA 128x128, BK=64, 3-stage cp.async, single sync per chunk.
// MODE 0: scatter into Q/K/V hi+lo (Q pre-scaled).  MODE 1: fp32 C.
// ---------------------------------------------------------------------------
#define BM 128
#define BN 128
#define BK 64
#define NCH 36                    // 3 sections x 12 chunks
#define GSTAGE 32768
#define GEMM_SMEM (3 * GSTAGE)

template <int MODE>
__global__ __launch_bounds__(256, 2)
void gemm_tc(const bf16* __restrict__ Ah, const bf16* __restrict__ Al,
             const bf16* __restrict__ Bh, const bf16* __restrict__ Bl,
             const float* __restrict__ bias, float* __restrict__ Cout, int Ntot)
{
    extern __shared__ char smem[];
    const uint32_t sb = smem_u32(smem);
    const int tid = threadIdx.x;
    const int warp = tid >> 5;
    const int lane = tid & 31;
    const int wm = (warp >> 1) * 32;
    const int wn = (warp & 1) * 64;
    const int bm = blockIdx.y * BM;
    const int bn = blockIdx.x * BN;

    float acc[2][8][4] = {};

    auto issue = [&](int c, int st) {
        int sec = c / 12;
        int cc  = c - sec * 12;
        const char* As = (const char*)((sec == 1) ? Al : Ah);
        const char* Bs = (const char*)((sec == 2) ? Bl : Bh);
        uint32_t abase = sb + st * GSTAGE;
        uint32_t bbase = abase + 16384;
        #pragma unroll
        for (int i = 0; i < 4; i++) {
            int id = tid + i * 256;
            int r = id >> 3, ch = id & 7;
            CP_ASYNC16(swz(abase, r, ch),
                       As + ((size_t)(bm + r) * NI + cc * BK) * 2 + ch * 16);
        }
        #pragma unroll
        for (int i = 0; i < 4; i++) {
            int id = tid + i * 256;
            int r = id >> 3, ch = id & 7;
            CP_ASYNC16(swz(bbase, r, ch),
                       Bs + ((size_t)(bn + r) * NI + cc * BK) * 2 + ch * 16);
        }
        CP_COMMIT();
    };

    issue(0, 0);
    issue(1, 1);

    for (int c = 0; c < NCH; c++) {
        const int st = c - (c / 3) * 3;
        if (c == NCH - 1) { CP_WAIT(0); } else { CP_WAIT(1); }
        __syncthreads();          // chunk c visible; all warps done with c-1
        if (c + 2 < NCH) issue(c + 2, (c + 2) - ((c + 2) / 3) * 3);

        uint32_t abase = sb + st * GSTAGE;
        uint32_t bbase = abase + 16384;
        const int t = lane >> 3;

        #pragma unroll
        for (int ks = 0; ks < 4; ks++) {
            uint32_t a[2][4];
            #pragma unroll
            for (int mt = 0; mt < 2; mt++) {
                int row = wm + mt * 16 + (t & 1) * 8 + (lane & 7);
                LDSM_X4(a[mt][0], a[mt][1], a[mt][2], a[mt][3],
                        swz(abase, row, 2 * ks + (t >> 1)));
            }
            #pragma unroll
            for (int ntp = 0; ntp < 4; ntp++) {
                uint32_t b4[4];
                int row = wn + (2 * ntp + ((lane >> 4) & 1)) * 8 + (lane & 7);
                LDSM_X4(b4[0], b4[1], b4[2], b4[3],
                        swz(bbase, row, 2 * ks + ((lane >> 3) & 1)));
                mma_bf16(acc[0][2 * ntp + 0], a[0], b4 + 0);
                mma_bf16(acc[1][2 * ntp + 0], a[1], b4 + 0);
                mma_bf16(acc[0][2 * ntp + 1], a[0], b4 + 2);
                mma_bf16(acc[1][2 * ntp + 1], a[1], b4 + 2);
            }
        }
        // no trailing sync: next iteration's sync provides the guard
    }

    // Epilogue
    #pragma unroll
    for (int mt = 0; mt < 2; mt++) {
        int gr0 = bm + wm + mt * 16 + (lane >> 2);
        #pragma unroll
        for (int nt = 0; nt < 8; nt++) {
            int c0 = bn + wn + nt * 8 + 2 * (lane & 3);
            float b0 = bias[c0], b1 = bias[c0 + 1];
            #pragma unroll
            for (int rr = 0; rr < 2; rr++) {
                int row = gr0 + rr * 8;
                float v0 = acc[mt][nt][rr * 2 + 0] + b0;
                float v1 = acc[mt][nt][rr * 2 + 1] + b1;
                if (MODE == 0) {
                    int h = c0 / 192;
                    int r = c0 - h * 192;
                    int w = r >> 6, dd = r & 63;
                    int b = row >> 11, sI = row & (SLEN - 1);
                    size_t off = ((size_t)((b * NH + h) * SLEN + sI)) * DH + dd;
                    if (w == 0) { v0 *= QSCALE; v1 *= QSCALE; }
                    bf16 h0 = __float2bfloat16(v0);
                    bf16 h1 = __float2bfloat16(v1);
                    bf16 l0 = __float2bfloat16(v0 - __bfloat162float(h0));
                    bf16 l1 = __float2bfloat16(v1 - __bfloat162float(h1));
                    bf16 *dh, *dl;
                    if (w == 0)      { dh = g_Qh; dl = g_Ql; }
                    else if (w == 1) { dh = g_Kh; dl = g_Kl; }
                    else             { dh = g_Vh; dl = g_Vl; }
                    *(bf162*)&dh[off] = bf162(h0, h1);
                    *(bf162*)&dl[off] = bf162(l0, l1);
                } else {
                    float2 v = make_float2(v0, v1);
                    *(float2*)&Cout[(size_t)row * Ntot + c0] = v;
                }
            }
        }
    }
}

// ---------------------------------------------------------------------------
// Flash attention on mma.sync (split-bf16, 3-term), max-free softmax (scale
// pre-folded into Q, base-2 exp).  CTA: 8 warps, Br=128, Bc=64. grid (16, 24).
// smem: Qh,Ql (16K each) + 2 stages x {Kh,Kl,Vh,Vl} (8K each)
// ---------------------------------------------------------------------------
#define ASTAGE 32768
#define ATTN_SMEM (32768 + 2 * ASTAGE)   // 98304
#define NKT (SLEN / 64)                  // 32

__global__ __launch_bounds__(256, 2)
void attn_kernel()
{
    extern __shared__ char smem[];
    const uint32_t sb = smem_u32(smem);
    const uint32_t qh_base = sb;
    const uint32_t ql_base = sb + 16384;
    const uint32_t stg_base = sb + 32768;

    const int tid  = threadIdx.x;
    const int warp = tid >> 5;
    const int lane = tid & 31;
    const int bh   = blockIdx.y;
    const int q0   = blockIdx.x * 128;

    const char* Qhg = (const char*)(g_Qh + ((size_t)bh * SLEN + q0) * DH);
    const char* Qlg = (const char*)(g_Ql + ((size_t)bh * SLEN + q0) * DH);
    const char* Khg = (const char*)(g_Kh + (size_t)bh * SLEN * DH);
    const char* Klg = (const char*)(g_Kl + (size_t)bh * SLEN * DH);
    const char* Vhg = (const char*)(g_Vh + (size_t)bh * SLEN * DH);
    const char* Vlg = (const char*)(g_Vl + (size_t)bh * SLEN * DH);

    // Q tiles: 2 x 128 rows x 128B  (own cp.async group)
    #pragma unroll
    for (int i = 0; i < 8; i++) {
        int id = tid + i * 256;
        int tile = id >> 10;
        int r = (id >> 3) & 127, ch = id & 7;
        const char* src = (tile == 0 ? Qhg : Qlg) + (size_t)r * 128 + ch * 16;
        CP_ASYNC16(swz(tile == 0 ? qh_base : ql_base, r, ch), src);
    }
    CP_COMMIT();

    auto issue_kv = [&](int kt, int st) {
        uint32_t base = stg_base + st * ASTAGE;
        size_t goff = (size_t)kt * 64 * 128;
        #pragma unroll
        for (int i = 0; i < 8; i++) {
            int id = tid + i * 256;
            int tile = id >> 9;
            int r = (id >> 3) & 63, ch = id & 7;
            const char* src;
            if      (tile == 0) src = Khg;
            else if (tile == 1) src = Klg;
            else if (tile == 2) src = Vhg;
            else                src = Vlg;
            src += goff + (size_t)r * 128 + ch * 16;
            CP_ASYNC16(swz(base + tile * 8192, r, ch), src);
        }
        CP_COMMIT();
    };

    issue_kv(0, 0);
    issue_kv(1, 1);

    CP_WAIT(2);                 // Q group done (kv0/kv1 may be in flight)
    __syncthreads();

    // Q fragments -> regs
    uint32_t qh[4][4], ql[4][4];
    {
        const int t = lane >> 3;
        int row = warp * 16 + (t & 1) * 8 + (lane & 7);
        #pragma unroll
        for (int ks = 0; ks < 4; ks++) {
            LDSM_X4(qh[ks][0], qh[ks][1], qh[ks][2], qh[ks][3],
                    swz(qh_base, row, 2 * ks + (t >> 1)));
            LDSM_X4(ql[ks][0], ql[ks][1], ql[ks][2], ql[ks][3],
                    swz(ql_base, row, 2 * ks + (t >> 1)));
        }
    }

    float l0 = 0.f, l1 = 0.f;
    float o[8][4] = {};

    for (int kt = 0; kt < NKT; kt++) {
        const int st = kt & 1;
        if (kt == NKT - 1) { CP_WAIT(0); } else { CP_WAIT(1); }
        __syncthreads();

        uint32_t khb = stg_base + st * ASTAGE;
        uint32_t klb = khb + 8192;
        uint32_t vhb = khb + 16384;
        uint32_t vlb = khb + 24576;

        // ---- S = (Q*c) K^T (3-term split) ----
        float s[8][4] = {};
        #pragma unroll
        for (int ks = 0; ks < 4; ks++) {
            #pragma unroll
            for (int ntp = 0; ntp < 4; ntp++) {
                int row = (2 * ntp + ((lane >> 4) & 1)) * 8 + (lane & 7);
                int ch = 2 * ks + ((lane >> 3) & 1);
                uint32_t bh4[4], bl4[4];
                LDSM_X4(bh4[0], bh4[1], bh4[2], bh4[3], swz(khb, row, ch));
                LDSM_X4(bl4[0], bl4[1], bl4[2], bl4[3], swz(klb, row, ch));
                mma_bf16(s[2 * ntp + 0], qh[ks], bh4 + 0);
                mma_bf16(s[2 * ntp + 0], ql[ks], bh4 + 0);
                mma_bf16(s[2 * ntp + 0], qh[ks], bl4 + 0);
                mma_bf16(s[2 * ntp + 1], qh[ks], bh4 + 2);
                mma_bf16(s[2 * ntp + 1], ql[ks], bh4 + 2);
                mma_bf16(s[2 * ntp + 1], qh[ks], bl4 + 2);
            }
        }

        // ---- max-free softmax: p = 2^s, accumulate row sums ----
        #pragma unroll
        for (int nt = 0; nt < 8; nt++) {
            s[nt][0] = ex2(s[nt][0]);
            s[nt][1] = ex2(s[nt][1]);
            s[nt][2] = ex2(s[nt][2]);
            s[nt][3] = ex2(s[nt][3]);
            l0 += s[nt][0] + s[nt][1];
            l1 += s[nt][2] + s[nt][3];
        }

        // ---- O += P V (3-term split) ----
        #pragma unroll
        for (int j = 0; j < 4; j++) {
            uint32_t ph[4], pl[4];
            #pragma unroll
            for (int half = 0; half < 2; half++) {
                float x0 = s[2 * j + half][0], y0 = s[2 * j + half][1];
                float x1 = s[2 * j + half][2], y1 = s[2 * j + half][3];
                bf16 hx0 = __float2bfloat16(x0), hy0 = __float2bfloat16(y0);
                bf16 hx1 = __float2bfloat16(x1), hy1 = __float2bfloat16(y1);
                ph[half * 2 + 0] = packbf(x0, y0);
                ph[half * 2 + 1] = packbf(x1, y1);
                pl[half * 2 + 0] = packbf(x0 - __bfloat162float(hx0),
                                          y0 - __bfloat162float(hy0));
                pl[half * 2 + 1] = packbf(x1 - __bfloat162float(hx1),
                                          y1 - __bfloat162float(hy1));
            }
            int row = j * 16 + ((lane >> 3) & 1) * 8 + (lane & 7);
            #pragma unroll
            for (int ntp = 0; ntp < 4; ntp++) {
                int ch = 2 * ntp + ((lane >> 4) & 1);
                uint32_t vh4[4], vl4[4];
                LDSM_X4_T(vh4[0], vh4[1], vh4[2], vh4[3], swz(vhb, row, ch));
                LDSM_X4_T(vl4[0], vl4[1], vl4[2], vl4[3], swz(vlb, row, ch));
                mma_bf16(o[2 * ntp + 0], ph, vh4 + 0);
                mma_bf16(o[2 * ntp + 0], pl, vh4 + 0);
                mma_bf16(o[2 * ntp + 0], ph, vl4 + 0);
                mma_bf16(o[2 * ntp + 1], ph, vh4 + 2);
                mma_bf16(o[2 * ntp + 1], pl, vh4 + 2);
                mma_bf16(o[2 * ntp + 1], ph, vl4 + 2);
            }
        }

        __syncthreads();          // all warps done with stage st
        if (kt + 2 < NKT) issue_kv(kt + 2, st);
    }

    // final row sums: reduce across the 4 lanes of the quad
    l0 += __shfl_xor_sync(0xffffffffu, l0, 1);
    l0 += __shfl_xor_sync(0xffffffffu, l0, 2);
    l1 += __shfl_xor_sync(0xffffffffu, l1, 1);
    l1 += __shfl_xor_sync(0xffffffffu, l1, 2);
    float inv0 = 1.0f / l0, inv1 = 1.0f / l1;

    // ---- epilogue -> g_Ah/g_Al (merged heads, split for proj GEMM) ----
    const int b = bh / NH, h = bh - (bh / NH) * NH;
    const int qr = q0 + warp * 16 + (lane >> 2);
    #pragma unroll
    for (int rr = 0; rr < 2; rr++) {
        size_t m = (size_t)b * SLEN + qr + rr * 8;
        float inv = rr ? inv1 : inv0;
        #pragma unroll
        for (int nt = 0; nt < 8; nt++) {
            int c = h * DH + nt * 8 + 2 * (lane & 3);
            float v0 = o[nt][rr * 2 + 0] * inv;
            float v1 = o[nt][rr * 2 + 1] * inv;
            bf16 h0 = __float2bfloat16(v0);
            bf16 h1 = __float2bfloat16(v1);
            bf16 e0 = __float2bfloat16(v0 - __bfloat162float(h0));
            bf16 e1 = __float2bfloat16(v1 - __bfloat162float(h1));
            size_t base = m * NI + c;
            *(bf162*)&g_Ah[base] = bf162(h0, h1);
            *(bf162*)&g_Al[base] = bf162(e0, e1);
        }
    }
}

// ---------------------------------------------------------------------------
extern "C" void kernel_launch(void* const* d_in, const int* in_sizes, int n_in,
                              void* d_out, int out_size)
{
    const float* inp   = (const float*)d_in[0];
    const float* Wqkv  = (const float*)d_in[1];
    const float* bqkv  = (const float*)d_in[2];
    const float* Wproj = (const float*)d_in[3];
    const float* bproj = (const float*)d_in[4];
    float* out = (float*)d_out;

    bf16 *ah, *al, *wqh, *wql, *wph, *wpl;
    cudaGetSymbolAddress((void**)&ah,  g_Ah);
    cudaGetSymbolAddress((void**)&al,  g_Al);
    cudaGetSymbolAddress((void**)&wqh, g_Wqh);
    cudaGetSymbolAddress((void**)&wql, g_Wql);
    cudaGetSymbolAddress((void**)&wph, g_Wph);
    cudaGetSymbolAddress((void**)&wpl, g_Wpl);

    cudaFuncSetAttribute(gemm_tc<0>,
                         cudaFuncAttributeMaxDynamicSharedMemorySize, GEMM_SMEM);
    cudaFuncSetAttribute(gemm_tc<1>,
                         cudaFuncAttributeMaxDynamicSharedMemorySize, GEMM_SMEM);
    cudaFuncSetAttribute(attn_kernel,
                         cudaFuncAttributeMaxDynamicSharedMemorySize, ATTN_SMEM);

    // 1) splits
    {
        int n = MTOT * NI;
        split_act_kernel<<<(n + 255) / 256, 256>>>(inp);
        dim3 blk(32, 8);
        split_w_kernel<<<dim3(3 * NI / 32, NI / 32), blk>>>(Wqkv, wqh, wql, 3 * NI);
        split_w_kernel<<<dim3(NI / 32, NI / 32), blk>>>(Wproj, wph, wpl, NI);
    }
    // 2) QKV GEMM + split scatter into Q/K/V hi/lo (Q pre-scaled)
    {
        dim3 grid(3 * NI / BN, MTOT / BM);   // (18, 32)
        gemm_tc<0><<<grid, 256, GEMM_SMEM>>>(ah, al, wqh, wql, bqkv, nullptr, 3 * NI);
    }
    // 3) Flash attention (mma.sync), writes split O for proj
    {
        dim3 grid(SLEN / 128, NBH);          // (16, 24)
        attn_kernel<<<grid, 256, ATTN_SMEM>>>();
    }
    // 4) proj GEMM -> out
    {
        dim3 grid(NI / BN, MTOT / BM);       // (6, 32)
        gemm_tc<1><<<grid, 256, GEMM_SMEM>>>(ah, al, wph, wpl, bproj, out, NI);
    }
}